// round 5
// baseline (speedup 1.0000x reference)
#include <cuda_runtime.h>
#include <math.h>
#include <stdint.h>

#define DIM 768
#define NHEAD 16
#define HD 48
#define SEQ 2048
#define ATTN_SCALE 0.14433756729740643f  // 1/sqrt(48)

#define BQ 128
#define BKV 64
#define NIT (SEQ / BKV)   // 32

// ---------------------------------------------------------------------------
// Scratch (device globals: allocation-guard-safe)
// ---------------------------------------------------------------------------
__device__ float g_q[8192 * DIM];
__device__ float g_k[8192 * DIM];
__device__ float g_v[8192 * DIM];
__device__ float g_ao[8192 * DIM];

// ---------------------------------------------------------------------------
// helpers
// ---------------------------------------------------------------------------
__device__ __forceinline__ uint32_t f2tf(float x) {
    uint32_t r;
    asm("cvt.rna.tf32.f32 %0, %1;" : "=r"(r) : "f"(x));
    return r;
}

__device__ __forceinline__ float fexp2(float x) {
    float y;
    asm("ex2.approx.f32 %0, %1;" : "=f"(y) : "f"(x));
    return y;
}

__device__ __forceinline__ void cp16(uint32_t dst, const void* src) {
    asm volatile("cp.async.cg.shared.global [%0], [%1], 16;\n"
                 :: "r"(dst), "l"(src));
}
__device__ __forceinline__ void cp_commit() {
    asm volatile("cp.async.commit_group;\n");
}
template <int N>
__device__ __forceinline__ void cp_wait() {
    asm volatile("cp.async.wait_group %0;\n" :: "n"(N));
}

// D = A(16x8, row) * B(8x8, col) + D, fp32 accum
__device__ __forceinline__ void mma_tf32(float* c, const uint32_t* a,
                                         uint32_t b0, uint32_t b1) {
    asm volatile(
        "mma.sync.aligned.m16n8k8.row.col.f32.tf32.tf32.f32 "
        "{%0,%1,%2,%3}, {%4,%5,%6,%7}, {%8,%9}, {%0,%1,%2,%3};\n"
        : "+f"(c[0]), "+f"(c[1]), "+f"(c[2]), "+f"(c[3])
        : "r"(a[0]), "r"(a[1]), "r"(a[2]), "r"(a[3]), "r"(b0), "r"(b1));
}

// ---------------------------------------------------------------------------
// GEMM (tf32 tensor core): C[m][n] = sum_k A[m][k]*W[n][k] + bias[n]
// Block tile 128x128, bk=16, 256 threads = 8 warps (2M x 4N).
// round_out != 0: round result to tf32 (rna) on store, so downstream
// kernels may feed the raw bits straight into tf32 MMA with no bias.
// ---------------------------------------------------------------------------
__global__ __launch_bounds__(256) void gemm_nt_bias_tf32(
    const float* __restrict__ A, const float* __restrict__ W,
    const float* __restrict__ bias, float* __restrict__ C,
    int M, int N, int K, int round_out)
{
    __shared__ __align__(16) uint32_t As[128 * 20];
    __shared__ __align__(16) uint32_t Ws[128 * 20];

    const int tid  = threadIdx.x;
    const int lane = tid & 31;
    const int warp = tid >> 5;
    const int wm   = (warp >> 2) * 64;
    const int wn   = (warp & 3) * 32;
    const int g    = lane >> 2;
    const int tq   = lane & 3;

    const int bm = blockIdx.y * 128;
    const int bn = blockIdx.x * 128;

    const int r0 = tid >> 2;
    const int c4 = (tid & 3) << 2;

    float acc[4][4][4];
#pragma unroll
    for (int mi = 0; mi < 4; mi++)
#pragma unroll
        for (int ni = 0; ni < 4; ni++)
#pragma unroll
            for (int j = 0; j < 4; j++) acc[mi][ni][j] = 0.f;

    float4 pa0 = *(const float4*)(A + (size_t)(bm + r0) * K + c4);
    float4 pa1 = *(const float4*)(A + (size_t)(bm + r0 + 64) * K + c4);
    float4 pw0 = *(const float4*)(W + (size_t)(bn + r0) * K + c4);
    float4 pw1 = *(const float4*)(W + (size_t)(bn + r0 + 64) * K + c4);

    for (int k0 = 0; k0 < K; k0 += 16) {
        uint4 ua0 = make_uint4(f2tf(pa0.x), f2tf(pa0.y), f2tf(pa0.z), f2tf(pa0.w));
        uint4 ua1 = make_uint4(f2tf(pa1.x), f2tf(pa1.y), f2tf(pa1.z), f2tf(pa1.w));
        uint4 uw0 = make_uint4(f2tf(pw0.x), f2tf(pw0.y), f2tf(pw0.z), f2tf(pw0.w));
        uint4 uw1 = make_uint4(f2tf(pw1.x), f2tf(pw1.y), f2tf(pw1.z), f2tf(pw1.w));
        *(uint4*)&As[r0 * 20 + c4]        = ua0;
        *(uint4*)&As[(r0 + 64) * 20 + c4] = ua1;
        *(uint4*)&Ws[r0 * 20 + c4]        = uw0;
        *(uint4*)&Ws[(r0 + 64) * 20 + c4] = uw1;
        __syncthreads();

        if (k0 + 16 < K) {
            pa0 = *(const float4*)(A + (size_t)(bm + r0) * K + k0 + 16 + c4);
            pa1 = *(const float4*)(A + (size_t)(bm + r0 + 64) * K + k0 + 16 + c4);
            pw0 = *(const float4*)(W + (size_t)(bn + r0) * K + k0 + 16 + c4);
            pw1 = *(const float4*)(W + (size_t)(bn + r0 + 64) * K + k0 + 16 + c4);
        }

#pragma unroll
        for (int ks = 0; ks < 2; ks++) {
            const int kb = ks * 8;
            uint32_t af[4][4], bf[4][2];
#pragma unroll
            for (int mi = 0; mi < 4; mi++) {
                const int m = wm + mi * 16;
                af[mi][0] = As[(m + g) * 20 + kb + tq];
                af[mi][1] = As[(m + 8 + g) * 20 + kb + tq];
                af[mi][2] = As[(m + g) * 20 + kb + 4 + tq];
                af[mi][3] = As[(m + 8 + g) * 20 + kb + 4 + tq];
            }
#pragma unroll
            for (int ni = 0; ni < 4; ni++) {
                const int n = wn + ni * 8;
                bf[ni][0] = Ws[(n + g) * 20 + kb + tq];
                bf[ni][1] = Ws[(n + g) * 20 + kb + 4 + tq];
            }
#pragma unroll
            for (int mi = 0; mi < 4; mi++)
#pragma unroll
                for (int ni = 0; ni < 4; ni++)
                    mma_tf32(acc[mi][ni], af[mi], bf[ni][0], bf[ni][1]);
        }
        __syncthreads();
    }

#pragma unroll
    for (int ni = 0; ni < 4; ni++) {
        const int col = bn + wn + ni * 8 + 2 * tq;
        const float2 bb = *(const float2*)(bias + col);
#pragma unroll
        for (int mi = 0; mi < 4; mi++) {
            const int row = bm + wm + mi * 16 + g;
            float2 v0, v1;
            v0.x = acc[mi][ni][0] + bb.x;
            v0.y = acc[mi][ni][1] + bb.y;
            v1.x = acc[mi][ni][2] + bb.x;
            v1.y = acc[mi][ni][3] + bb.y;
            if (round_out) {
                v0.x = __uint_as_float(f2tf(v0.x));
                v0.y = __uint_as_float(f2tf(v0.y));
                v1.x = __uint_as_float(f2tf(v1.x));
                v1.y = __uint_as_float(f2tf(v1.y));
            }
            *(float2*)(C + (size_t)row * N + col)       = v0;
            *(float2*)(C + (size_t)(row + 8) * N + col) = v1;
        }
    }
}

// ---------------------------------------------------------------------------
// Flash attention v4 (tf32 mma + cp.async double-buffered K/V).
// Inputs Q/K/V are pre-rounded to tf32 by the projection GEMMs, so raw bits
// go straight into the MMAs. Softmax scale folded into the exp2 constant.
//
// Block = 128 q rows of one (b,h), 128 threads = 4 warps; warp owns 32 rows
// (2 m16 subtiles). kv tiles of 64, double-buffered.
//
// Shared (uint32 words):
//   Ps[128][72]            ofs 0      9216  (aliases Qs[128][52] staging)
//   Ks[2][64][52]          ofs 9216   6656
//   Vs[2][64][56]          ofs 15872  7168
// total 23040 words = 92160 bytes
// ---------------------------------------------------------------------------
__global__ __launch_bounds__(128) void flash_attn_tf32_v4(
    const float* __restrict__ Q, const float* __restrict__ K,
    const float* __restrict__ V, float* __restrict__ O)
{
    extern __shared__ uint32_t usm[];
    uint32_t* Ps = usm;                       // [128][72]
    const uint32_t sbase = (uint32_t)__cvta_generic_to_shared(usm);

    const int tid  = threadIdx.x;
    const int lane = tid & 31;
    const int w    = tid >> 5;
    const int g    = lane >> 2;
    const int tq   = lane & 3;
    const int qw   = w * 32;

    const int h  = blockIdx.y;
    const int b  = blockIdx.z;
    const int q0 = blockIdx.x * BQ;

    const float* Qb = Q + ((size_t)(b * SEQ + q0)) * DIM + h * HD;
    const float* Kb = K + (size_t)b * SEQ * DIM + h * HD;
    const float* Vb = V + (size_t)b * SEQ * DIM + h * HD;

    const int sr = tid / 12;            // staging row helpers (not used for cp)
    (void)sr;

    // ---- kick off async K/V load for tile 0 ----
    {
        const uint32_t kdst = sbase + 9216u * 4u;
        const uint32_t vdst = sbase + 15872u * 4u;
#pragma unroll
        for (int i = 0; i < 6; i++) {
            int idx = tid + i * 128;
            int r   = idx / 12;
            int c4  = (idx % 12) << 2;
            cp16(kdst + (uint32_t)(r * 52 + c4) * 4u, Kb + (size_t)r * DIM + c4);
            cp16(vdst + (uint32_t)(r * 56 + c4) * 4u, Vb + (size_t)r * DIM + c4);
        }
        cp_commit();
    }

    // ---- stage Q (raw bits; scale folded into exp2 later) ----
#pragma unroll
    for (int i = 0; i < 12; i++) {
        int idx = tid + i * 128;
        int r   = idx / 12;
        int c4  = (idx % 12) << 2;
        float4 f = *(const float4*)(Qb + (size_t)r * DIM + c4);
        *(float4*)&usm[r * 52 + c4] = f;
    }
    __syncthreads();

    // persistent Q fragments: 2 subtiles x 6 k8 steps
    uint32_t qf[2][6][4];
#pragma unroll
    for (int sub = 0; sub < 2; sub++) {
        const int qb = qw + sub * 16;
#pragma unroll
        for (int kt = 0; kt < 6; kt++) {
            const int kb = kt * 8;
            qf[sub][kt][0] = usm[(qb + g) * 52 + kb + tq];
            qf[sub][kt][1] = usm[(qb + 8 + g) * 52 + kb + tq];
            qf[sub][kt][2] = usm[(qb + g) * 52 + kb + 4 + tq];
            qf[sub][kt][3] = usm[(qb + 8 + g) * 52 + kb + 4 + tq];
        }
    }

    float oacc[2][6][4];
#pragma unroll
    for (int sub = 0; sub < 2; sub++)
#pragma unroll
        for (int ni = 0; ni < 6; ni++)
#pragma unroll
            for (int j = 0; j < 4; j++) oacc[sub][ni][j] = 0.f;
    float mrow[2][2] = {{-1e30f, -1e30f}, {-1e30f, -1e30f}};
    float lrow[2][2] = {{0.f, 0.f}, {0.f, 0.f}};

    const float CE = ATTN_SCALE * 1.4426950408889634f;  // scale * log2(e)

    for (int it = 0; it < NIT; it++) {
        // issue next tile's async loads (into buffer (it+1)&1)
        if (it + 1 < NIT) {
            const int bi = (it + 1) & 1;
            const int kv0 = (it + 1) * BKV;
            const uint32_t kdst = sbase + (uint32_t)(9216 + bi * 3328) * 4u;
            const uint32_t vdst = sbase + (uint32_t)(15872 + bi * 3584) * 4u;
#pragma unroll
            for (int i = 0; i < 6; i++) {
                int idx = tid + i * 128;
                int r   = idx / 12;
                int c4  = (idx % 12) << 2;
                cp16(kdst + (uint32_t)(r * 52 + c4) * 4u,
                     Kb + (size_t)(kv0 + r) * DIM + c4);
                cp16(vdst + (uint32_t)(r * 56 + c4) * 4u,
                     Vb + (size_t)(kv0 + r) * DIM + c4);
            }
            cp_commit();
            cp_wait<1>();
        } else {
            cp_wait<0>();
        }
        __syncthreads();

        const uint32_t* Ksb = usm + 9216 + (it & 1) * 3328;
        const uint32_t* Vsb = usm + 15872 + (it & 1) * 3584;

        // ---- per subtile: S = Q K^T, softmax, write P ----
#pragma unroll
        for (int sub = 0; sub < 2; sub++) {
            const int qb = qw + sub * 16;

            float sacc[8][4];
#pragma unroll
            for (int ni = 0; ni < 8; ni++)
#pragma unroll
                for (int j = 0; j < 4; j++) sacc[ni][j] = 0.f;

#pragma unroll
            for (int kt = 0; kt < 6; kt++) {
                const int kb = kt * 8;
#pragma unroll
                for (int ni = 0; ni < 8; ni++) {
                    const int n = ni * 8;
                    uint32_t b0 = Ksb[(n + g) * 52 + kb + tq];
                    uint32_t b1 = Ksb[(n + g) * 52 + kb + 4 + tq];
                    mma_tf32(sacc[ni], qf[sub][kt], b0, b1);
                }
            }

            // online softmax in raw-s domain, scale folded into CE
            float mx0 = -1e30f, mx1 = -1e30f;
#pragma unroll
            for (int ni = 0; ni < 8; ni++) {
                mx0 = fmaxf(mx0, fmaxf(sacc[ni][0], sacc[ni][1]));
                mx1 = fmaxf(mx1, fmaxf(sacc[ni][2], sacc[ni][3]));
            }
            mx0 = fmaxf(mx0, __shfl_xor_sync(0xffffffffu, mx0, 1));
            mx0 = fmaxf(mx0, __shfl_xor_sync(0xffffffffu, mx0, 2));
            mx1 = fmaxf(mx1, __shfl_xor_sync(0xffffffffu, mx1, 1));
            mx1 = fmaxf(mx1, __shfl_xor_sync(0xffffffffu, mx1, 2));

            const float mn0 = fmaxf(mrow[sub][0], mx0);
            const float mn1 = fmaxf(mrow[sub][1], mx1);
            const float cr0 = fexp2((mrow[sub][0] - mn0) * CE);
            const float cr1 = fexp2((mrow[sub][1] - mn1) * CE);
            mrow[sub][0] = mn0; mrow[sub][1] = mn1;

            float rs0 = 0.f, rs1 = 0.f;
#pragma unroll
            for (int ni = 0; ni < 8; ni++) {
                sacc[ni][0] = fexp2((sacc[ni][0] - mn0) * CE);
                sacc[ni][1] = fexp2((sacc[ni][1] - mn0) * CE);
                sacc[ni][2] = fexp2((sacc[ni][2] - mn1) * CE);
                sacc[ni][3] = fexp2((sacc[ni][3] - mn1) * CE);
                rs0 += sacc[ni][0] + sacc[ni][1];
                rs1 += sacc[ni][2] + sacc[ni][3];
            }
            rs0 += __shfl_xor_sync(0xffffffffu, rs0, 1);
            rs0 += __shfl_xor_sync(0xffffffffu, rs0, 2);
            rs1 += __shfl_xor_sync(0xffffffffu, rs1, 1);
            rs1 += __shfl_xor_sync(0xffffffffu, rs1, 2);
            lrow[sub][0] = lrow[sub][0] * cr0 + rs0;
            lrow[sub][1] = lrow[sub][1] * cr1 + rs1;

#pragma unroll
            for (int ni = 0; ni < 6; ni++) {
                oacc[sub][ni][0] *= cr0; oacc[sub][ni][1] *= cr0;
                oacc[sub][ni][2] *= cr1; oacc[sub][ni][3] *= cr1;
            }

            // write P (tf32 rna) to this warp's rows (stride 72: CF)
#pragma unroll
            for (int ni = 0; ni < 8; ni++) {
                const int col = ni * 8 + 2 * tq;
                uint2 p0 = make_uint2(f2tf(sacc[ni][0]), f2tf(sacc[ni][1]));
                uint2 p1 = make_uint2(f2tf(sacc[ni][2]), f2tf(sacc[ni][3]));
                *(uint2*)&Ps[(qb + g) * 72 + col]     = p0;
                *(uint2*)&Ps[(qb + 8 + g) * 72 + col] = p1;
            }
        }
        __syncwarp();  // P is warp-local

        // ---- O += P V ----
#pragma unroll
        for (int sub = 0; sub < 2; sub++) {
            const int qb = qw + sub * 16;
#pragma unroll
            for (int kt = 0; kt < 8; kt++) {
                const int kb = kt * 8;
                uint32_t af[4];
                af[0] = Ps[(qb + g) * 72 + kb + tq];
                af[1] = Ps[(qb + 8 + g) * 72 + kb + tq];
                af[2] = Ps[(qb + g) * 72 + kb + 4 + tq];
                af[3] = Ps[(qb + 8 + g) * 72 + kb + 4 + tq];
#pragma unroll
                for (int ni = 0; ni < 6; ni++) {
                    const int n = ni * 8;
                    uint32_t b0 = Vsb[(kb + tq) * 56 + n + g];
                    uint32_t b1 = Vsb[(kb + 4 + tq) * 56 + n + g];
                    mma_tf32(oacc[sub][ni], af, b0, b1);
                }
            }
        }
        __syncthreads();  // all compute done before next iter's cp.async overwrites
    }

    // ---- epilogue ----
#pragma unroll
    for (int sub = 0; sub < 2; sub++) {
        const float inv0 = 1.f / lrow[sub][0];
        const float inv1 = 1.f / lrow[sub][1];
        float* Ob = O + ((size_t)(b * SEQ + q0 + qw + sub * 16)) * DIM + h * HD;
#pragma unroll
        for (int ni = 0; ni < 6; ni++) {
            const int col = ni * 8 + 2 * tq;
            float2 v0, v1;
            v0.x = oacc[sub][ni][0] * inv0; v0.y = oacc[sub][ni][1] * inv0;
            v1.x = oacc[sub][ni][2] * inv1; v1.y = oacc[sub][ni][3] * inv1;
            *(float2*)(Ob + (size_t)g * DIM + col)       = v0;
            *(float2*)(Ob + (size_t)(g + 8) * DIM + col) = v1;
        }
    }
}

// ---------------------------------------------------------------------------
// launch
// ---------------------------------------------------------------------------
extern "C" void kernel_launch(void* const* d_in, const int* in_sizes, int n_in,
                              void* d_out, int out_size)
{
    const float* x  = (const float*)d_in[0];
    const float* Wq = (const float*)d_in[1];
    const float* bq = (const float*)d_in[2];
    const float* Wk = (const float*)d_in[3];
    const float* bk = (const float*)d_in[4];
    const float* Wv = (const float*)d_in[5];
    const float* bv = (const float*)d_in[6];
    const float* Wo = (const float*)d_in[7];
    const float* bo = (const float*)d_in[8];
    float* out = (float*)d_out;

    const int M = in_sizes[0] / DIM;   // B*S = 8192
    const int B = M / SEQ;             // 4

    float *qp, *kp, *vp, *aop;
    cudaGetSymbolAddress((void**)&qp,  g_q);
    cudaGetSymbolAddress((void**)&kp,  g_k);
    cudaGetSymbolAddress((void**)&vp,  g_v);
    cudaGetSymbolAddress((void**)&aop, g_ao);

    const int attn_smem = 23040 * 4;   // 92160 bytes
    cudaFuncSetAttribute(flash_attn_tf32_v4,
                         cudaFuncAttributeMaxDynamicSharedMemorySize, attn_smem);

    dim3 ggrid(DIM / 128, M / 128);    // (6, 64)
    gemm_nt_bias_tf32<<<ggrid, 256>>>(x, Wq, bq, qp, M, DIM, DIM, 1);
    gemm_nt_bias_tf32<<<ggrid, 256>>>(x, Wk, bk, kp, M, DIM, DIM, 1);
    gemm_nt_bias_tf32<<<ggrid, 256>>>(x, Wv, bv, vp, M, DIM, DIM, 1);

    dim3 agrid(SEQ / BQ, NHEAD, B);    // (16, 16, 4)
    flash_attn_tf32_v4<<<agrid, 128, attn_smem>>>(qp, kp, vp, aop);

    gemm_nt_bias_tf32<<<ggrid, 256>>>(aop, Wo, bo, out, M, DIM, DIM, 0);
}

// round 6
// speedup vs baseline: 1.4797x; 1.4797x over previous
#include <cuda_runtime.h>
#include <math.h>
#include <stdint.h>

#define DIM 768
#define NHEAD 16
#define HD 48
#define SEQ 2048
#define ATTN_SCALE 0.14433756729740643f  // 1/sqrt(48)

#define BQ 128
#define BKV 64

// ---------------------------------------------------------------------------
// Scratch (device globals: allocation-guard-safe)
// ---------------------------------------------------------------------------
__device__ float g_q[8192 * DIM];
__device__ float g_k[8192 * DIM];
__device__ float g_v[8192 * DIM];
__device__ float g_ao[8192 * DIM];

// ---------------------------------------------------------------------------
// helpers
// ---------------------------------------------------------------------------
__device__ __forceinline__ uint32_t f2tf(float x) {
    uint32_t r;
    asm("cvt.rna.tf32.f32 %0, %1;" : "=r"(r) : "f"(x));
    return r;
}

__device__ __forceinline__ float fexp2(float x) {
    float y;
    asm("ex2.approx.f32 %0, %1;" : "=f"(y) : "f"(x));
    return y;
}

// D = A(16x8, row) * B(8x8, col) + D, fp32 accum
__device__ __forceinline__ void mma_tf32(float* c, const uint32_t* a,
                                         uint32_t b0, uint32_t b1) {
    asm volatile(
        "mma.sync.aligned.m16n8k8.row.col.f32.tf32.tf32.f32 "
        "{%0,%1,%2,%3}, {%4,%5,%6,%7}, {%8,%9}, {%0,%1,%2,%3};\n"
        : "+f"(c[0]), "+f"(c[1]), "+f"(c[2]), "+f"(c[3])
        : "r"(a[0]), "r"(a[1]), "r"(a[2]), "r"(a[3]), "r"(b0), "r"(b1));
}

// ---------------------------------------------------------------------------
// GEMM (tf32 tensor core): C[m][n] = sum_k A[m][k]*W[n][k] + bias[n]
// Block tile 128x128, bk=16, 256 threads = 8 warps (2M x 4N),
// warp tile 64x32 = 4x4 m16n8 tiles. Register-prefetch double buffer.
// (identical to the R3 version, which measured fastest)
// ---------------------------------------------------------------------------
__global__ __launch_bounds__(256) void gemm_nt_bias_tf32(
    const float* __restrict__ A, const float* __restrict__ W,
    const float* __restrict__ bias, float* __restrict__ C,
    int M, int N, int K)
{
    __shared__ __align__(16) uint32_t As[128 * 20];
    __shared__ __align__(16) uint32_t Ws[128 * 20];

    const int tid  = threadIdx.x;
    const int lane = tid & 31;
    const int warp = tid >> 5;
    const int wm   = (warp >> 2) * 64;
    const int wn   = (warp & 3) * 32;
    const int g    = lane >> 2;
    const int tq   = lane & 3;

    const int bm = blockIdx.y * 128;
    const int bn = blockIdx.x * 128;

    const int r0 = tid >> 2;
    const int c4 = (tid & 3) << 2;

    float acc[4][4][4];
#pragma unroll
    for (int mi = 0; mi < 4; mi++)
#pragma unroll
        for (int ni = 0; ni < 4; ni++)
#pragma unroll
            for (int j = 0; j < 4; j++) acc[mi][ni][j] = 0.f;

    float4 pa0 = *(const float4*)(A + (size_t)(bm + r0) * K + c4);
    float4 pa1 = *(const float4*)(A + (size_t)(bm + r0 + 64) * K + c4);
    float4 pw0 = *(const float4*)(W + (size_t)(bn + r0) * K + c4);
    float4 pw1 = *(const float4*)(W + (size_t)(bn + r0 + 64) * K + c4);

    for (int k0 = 0; k0 < K; k0 += 16) {
        uint4 ua0 = make_uint4(f2tf(pa0.x), f2tf(pa0.y), f2tf(pa0.z), f2tf(pa0.w));
        uint4 ua1 = make_uint4(f2tf(pa1.x), f2tf(pa1.y), f2tf(pa1.z), f2tf(pa1.w));
        uint4 uw0 = make_uint4(f2tf(pw0.x), f2tf(pw0.y), f2tf(pw0.z), f2tf(pw0.w));
        uint4 uw1 = make_uint4(f2tf(pw1.x), f2tf(pw1.y), f2tf(pw1.z), f2tf(pw1.w));
        *(uint4*)&As[r0 * 20 + c4]        = ua0;
        *(uint4*)&As[(r0 + 64) * 20 + c4] = ua1;
        *(uint4*)&Ws[r0 * 20 + c4]        = uw0;
        *(uint4*)&Ws[(r0 + 64) * 20 + c4] = uw1;
        __syncthreads();

        if (k0 + 16 < K) {
            pa0 = *(const float4*)(A + (size_t)(bm + r0) * K + k0 + 16 + c4);
            pa1 = *(const float4*)(A + (size_t)(bm + r0 + 64) * K + k0 + 16 + c4);
            pw0 = *(const float4*)(W + (size_t)(bn + r0) * K + k0 + 16 + c4);
            pw1 = *(const float4*)(W + (size_t)(bn + r0 + 64) * K + k0 + 16 + c4);
        }

#pragma unroll
        for (int ks = 0; ks < 2; ks++) {
            const int kb = ks * 8;
            uint32_t af[4][4], bf[4][2];
#pragma unroll
            for (int mi = 0; mi < 4; mi++) {
                const int m = wm + mi * 16;
                af[mi][0] = As[(m + g) * 20 + kb + tq];
                af[mi][1] = As[(m + 8 + g) * 20 + kb + tq];
                af[mi][2] = As[(m + g) * 20 + kb + 4 + tq];
                af[mi][3] = As[(m + 8 + g) * 20 + kb + 4 + tq];
            }
#pragma unroll
            for (int ni = 0; ni < 4; ni++) {
                const int n = wn + ni * 8;
                bf[ni][0] = Ws[(n + g) * 20 + kb + tq];
                bf[ni][1] = Ws[(n + g) * 20 + kb + 4 + tq];
            }
#pragma unroll
            for (int mi = 0; mi < 4; mi++)
#pragma unroll
                for (int ni = 0; ni < 4; ni++)
                    mma_tf32(acc[mi][ni], af[mi], bf[ni][0], bf[ni][1]);
        }
        __syncthreads();
    }

#pragma unroll
    for (int ni = 0; ni < 4; ni++) {
        const int col = bn + wn + ni * 8 + 2 * tq;
        const float2 bb = *(const float2*)(bias + col);
#pragma unroll
        for (int mi = 0; mi < 4; mi++) {
            const int row = bm + wm + mi * 16 + g;
            float2 v0, v1;
            v0.x = acc[mi][ni][0] + bb.x;
            v0.y = acc[mi][ni][1] + bb.y;
            v1.x = acc[mi][ni][2] + bb.x;
            v1.y = acc[mi][ni][3] + bb.y;
            *(float2*)(C + (size_t)row * N + col)       = v0;
            *(float2*)(C + (size_t)(row + 8) * N + col) = v1;
        }
    }
}

// ---------------------------------------------------------------------------
// Flash attention v5 (tf32 mma, LDG staging, K/V fragment loads hoisted
// across the two q-subtiles -> ~36% fewer shared-mem wavefronts vs R3).
// Block = 128 q rows of one (b,h), 128 threads = 4 warps; warp owns 32 rows
// (2 m16 subtiles, S-mma for both fed by ONE K-fragment load).
//
// Shared (uint32 words):
//   Ps[128][72]   ofs 0      9216  (aliases Qs[128][52] staging)
//   Ks[64][52]    ofs 9216   3328
//   Vs[64][56]    ofs 12544  3584
// total 16128 words = 64512 bytes.
// ---------------------------------------------------------------------------
__global__ __launch_bounds__(128) void flash_attn_tf32_v5(
    const float* __restrict__ Q, const float* __restrict__ K,
    const float* __restrict__ V, float* __restrict__ O)
{
    extern __shared__ uint32_t usm[];
    uint32_t* Ps = usm;              // [128][72]
    uint32_t* Qs = usm;              // [128][52] staging alias
    uint32_t* Ks = usm + 9216;       // [64][52]
    uint32_t* Vs = usm + 12544;      // [64][56]

    const int tid  = threadIdx.x;
    const int lane = tid & 31;
    const int w    = tid >> 5;
    const int g    = lane >> 2;
    const int tq   = lane & 3;
    const int qw   = w * 32;

    const int h  = blockIdx.y;
    const int b  = blockIdx.z;
    const int q0 = blockIdx.x * BQ;

    const float* Qb = Q + ((size_t)(b * SEQ + q0)) * DIM + h * HD;
    const float* Kb = K + (size_t)b * SEQ * DIM + h * HD;
    const float* Vb = V + (size_t)b * SEQ * DIM + h * HD;

    // ---- stage Q (tf32 rna, unscaled; scale folded into exp2 const) ----
#pragma unroll
    for (int i = 0; i < 12; i++) {
        int idx = tid + i * 128;
        int r   = idx / 12;
        int c4  = (idx % 12) << 2;
        float4 f = *(const float4*)(Qb + (size_t)r * DIM + c4);
        uint4 u = make_uint4(f2tf(f.x), f2tf(f.y), f2tf(f.z), f2tf(f.w));
        *(uint4*)&Qs[r * 52 + c4] = u;
    }
    __syncthreads();

    // persistent Q fragments: 2 subtiles x 6 k8 steps
    uint32_t qf[2][6][4];
#pragma unroll
    for (int sub = 0; sub < 2; sub++) {
        const int qb = qw + sub * 16;
#pragma unroll
        for (int kt = 0; kt < 6; kt++) {
            const int kb = kt * 8;
            qf[sub][kt][0] = Qs[(qb + g) * 52 + kb + tq];
            qf[sub][kt][1] = Qs[(qb + 8 + g) * 52 + kb + tq];
            qf[sub][kt][2] = Qs[(qb + g) * 52 + kb + 4 + tq];
            qf[sub][kt][3] = Qs[(qb + 8 + g) * 52 + kb + 4 + tq];
        }
    }

    float oacc[2][6][4];
#pragma unroll
    for (int sub = 0; sub < 2; sub++)
#pragma unroll
        for (int ni = 0; ni < 6; ni++)
#pragma unroll
            for (int j = 0; j < 4; j++) oacc[sub][ni][j] = 0.f;
    float mrow[2][2] = {{-1e30f, -1e30f}, {-1e30f, -1e30f}};
    float lrow[2][2] = {{0.f, 0.f}, {0.f, 0.f}};

    const float CE = ATTN_SCALE * 1.4426950408889634f;  // scale * log2(e)

    for (int kv0 = 0; kv0 < SEQ; kv0 += BKV) {
        __syncthreads();  // all consumers of Ks/Vs (and Qs on iter 0) done

        // ---- stage K, V tiles (tf32 rna) ----
#pragma unroll
        for (int i = 0; i < 6; i++) {
            int idx = tid + i * 128;
            int r   = idx / 12;
            int c4  = (idx % 12) << 2;
            float4 kf = *(const float4*)(Kb + (size_t)(kv0 + r) * DIM + c4);
            float4 vf = *(const float4*)(Vb + (size_t)(kv0 + r) * DIM + c4);
            *(uint4*)&Ks[r * 52 + c4] =
                make_uint4(f2tf(kf.x), f2tf(kf.y), f2tf(kf.z), f2tf(kf.w));
            *(uint4*)&Vs[r * 56 + c4] =
                make_uint4(f2tf(vf.x), f2tf(vf.y), f2tf(vf.z), f2tf(vf.w));
        }
        __syncthreads();

        // ---- S = Q K^T for BOTH subtiles, one K-fragment load each ----
        float sacc[2][8][4];
#pragma unroll
        for (int sub = 0; sub < 2; sub++)
#pragma unroll
            for (int ni = 0; ni < 8; ni++)
#pragma unroll
                for (int j = 0; j < 4; j++) sacc[sub][ni][j] = 0.f;

#pragma unroll
        for (int kt = 0; kt < 6; kt++) {
            const int kb = kt * 8;
#pragma unroll
            for (int ni = 0; ni < 8; ni++) {
                const int n = ni * 8;
                uint32_t b0 = Ks[(n + g) * 52 + kb + tq];
                uint32_t b1 = Ks[(n + g) * 52 + kb + 4 + tq];
                mma_tf32(sacc[0][ni], qf[0][kt], b0, b1);
                mma_tf32(sacc[1][ni], qf[1][kt], b0, b1);
            }
        }

        // ---- online softmax + P write, per subtile ----
#pragma unroll
        for (int sub = 0; sub < 2; sub++) {
            const int qb = qw + sub * 16;

            float mx0 = -1e30f, mx1 = -1e30f;
#pragma unroll
            for (int ni = 0; ni < 8; ni++) {
                mx0 = fmaxf(mx0, fmaxf(sacc[sub][ni][0], sacc[sub][ni][1]));
                mx1 = fmaxf(mx1, fmaxf(sacc[sub][ni][2], sacc[sub][ni][3]));
            }
            mx0 = fmaxf(mx0, __shfl_xor_sync(0xffffffffu, mx0, 1));
            mx0 = fmaxf(mx0, __shfl_xor_sync(0xffffffffu, mx0, 2));
            mx1 = fmaxf(mx1, __shfl_xor_sync(0xffffffffu, mx1, 1));
            mx1 = fmaxf(mx1, __shfl_xor_sync(0xffffffffu, mx1, 2));

            const float mn0 = fmaxf(mrow[sub][0], mx0);
            const float mn1 = fmaxf(mrow[sub][1], mx1);
            const float cr0 = fexp2((mrow[sub][0] - mn0) * CE);
            const float cr1 = fexp2((mrow[sub][1] - mn1) * CE);
            mrow[sub][0] = mn0; mrow[sub][1] = mn1;

            float rs0 = 0.f, rs1 = 0.f;
#pragma unroll
            for (int ni = 0; ni < 8; ni++) {
                float p0 = fexp2((sacc[sub][ni][0] - mn0) * CE);
                float p1 = fexp2((sacc[sub][ni][1] - mn0) * CE);
                float p2 = fexp2((sacc[sub][ni][2] - mn1) * CE);
                float p3 = fexp2((sacc[sub][ni][3] - mn1) * CE);
                rs0 += p0 + p1;
                rs1 += p2 + p3;
                const int col = ni * 8 + 2 * tq;
                *(uint2*)&Ps[(qb + g) * 72 + col] =
                    make_uint2(f2tf(p0), f2tf(p1));
                *(uint2*)&Ps[(qb + 8 + g) * 72 + col] =
                    make_uint2(f2tf(p2), f2tf(p3));
            }
            rs0 += __shfl_xor_sync(0xffffffffu, rs0, 1);
            rs0 += __shfl_xor_sync(0xffffffffu, rs0, 2);
            rs1 += __shfl_xor_sync(0xffffffffu, rs1, 1);
            rs1 += __shfl_xor_sync(0xffffffffu, rs1, 2);
            lrow[sub][0] = lrow[sub][0] * cr0 + rs0;
            lrow[sub][1] = lrow[sub][1] * cr1 + rs1;

#pragma unroll
            for (int ni = 0; ni < 6; ni++) {
                oacc[sub][ni][0] *= cr0; oacc[sub][ni][1] *= cr0;
                oacc[sub][ni][2] *= cr1; oacc[sub][ni][3] *= cr1;
            }
        }
        __syncwarp();  // P is warp-local

        // ---- O += P V, V fragments loaded ONCE for both subtiles ----
#pragma unroll
        for (int kt = 0; kt < 8; kt++) {
            const int kb = kt * 8;
            uint32_t af0[4], af1[4];
            af0[0] = Ps[(qw + g) * 72 + kb + tq];
            af0[1] = Ps[(qw + 8 + g) * 72 + kb + tq];
            af0[2] = Ps[(qw + g) * 72 + kb + 4 + tq];
            af0[3] = Ps[(qw + 8 + g) * 72 + kb + 4 + tq];
            af1[0] = Ps[(qw + 16 + g) * 72 + kb + tq];
            af1[1] = Ps[(qw + 24 + g) * 72 + kb + tq];
            af1[2] = Ps[(qw + 16 + g) * 72 + kb + 4 + tq];
            af1[3] = Ps[(qw + 24 + g) * 72 + kb + 4 + tq];
#pragma unroll
            for (int ni = 0; ni < 6; ni++) {
                const int n = ni * 8;
                uint32_t b0 = Vs[(kb + tq) * 56 + n + g];
                uint32_t b1 = Vs[(kb + 4 + tq) * 56 + n + g];
                mma_tf32(oacc[0][ni], af0, b0, b1);
                mma_tf32(oacc[1][ni], af1, b0, b1);
            }
        }
    }

    // ---- epilogue ----
#pragma unroll
    for (int sub = 0; sub < 2; sub++) {
        const float inv0 = 1.f / lrow[sub][0];
        const float inv1 = 1.f / lrow[sub][1];
        float* Ob = O + ((size_t)(b * SEQ + q0 + qw + sub * 16)) * DIM + h * HD;
#pragma unroll
        for (int ni = 0; ni < 6; ni++) {
            const int col = ni * 8 + 2 * tq;
            float2 v0, v1;
            v0.x = oacc[sub][ni][0] * inv0; v0.y = oacc[sub][ni][1] * inv0;
            v1.x = oacc[sub][ni][2] * inv1; v1.y = oacc[sub][ni][3] * inv1;
            *(float2*)(Ob + (size_t)g * DIM + col)       = v0;
            *(float2*)(Ob + (size_t)(g + 8) * DIM + col) = v1;
        }
    }
}

// ---------------------------------------------------------------------------
// launch
// ---------------------------------------------------------------------------
extern "C" void kernel_launch(void* const* d_in, const int* in_sizes, int n_in,
                              void* d_out, int out_size)
{
    const float* x  = (const float*)d_in[0];
    const float* Wq = (const float*)d_in[1];
    const float* bq = (const float*)d_in[2];
    const float* Wk = (const float*)d_in[3];
    const float* bk = (const float*)d_in[4];
    const float* Wv = (const float*)d_in[5];
    const float* bv = (const float*)d_in[6];
    const float* Wo = (const float*)d_in[7];
    const float* bo = (const float*)d_in[8];
    float* out = (float*)d_out;

    const int M = in_sizes[0] / DIM;   // B*S = 8192
    const int B = M / SEQ;             // 4

    float *qp, *kp, *vp, *aop;
    cudaGetSymbolAddress((void**)&qp,  g_q);
    cudaGetSymbolAddress((void**)&kp,  g_k);
    cudaGetSymbolAddress((void**)&vp,  g_v);
    cudaGetSymbolAddress((void**)&aop, g_ao);

    const int attn_smem = 16128 * 4;   // 64512 bytes
    cudaFuncSetAttribute(flash_attn_tf32_v5,
                         cudaFuncAttributeMaxDynamicSharedMemorySize, attn_smem);

    dim3 ggrid(DIM / 128, M / 128);    // (6, 64)
    gemm_nt_bias_tf32<<<ggrid, 256>>>(x, Wq, bq, qp, M, DIM, DIM);
    gemm_nt_bias_tf32<<<ggrid, 256>>>(x, Wk, bk, kp, M, DIM, DIM);
    gemm_nt_bias_tf32<<<ggrid, 256>>>(x, Wv, bv, vp, M, DIM, DIM);

    dim3 agrid(SEQ / BQ, NHEAD, B);    // (16, 16, 4)
    flash_attn_tf32_v5<<<agrid, 128, attn_smem>>>(qp, kp, vp, aop);

    gemm_nt_bias_tf32<<<ggrid, 256>>>(aop, Wo, bo, out, M, DIM, DIM);
}

// round 7
// speedup vs baseline: 2.4011x; 1.6227x over previous
#include <cuda_runtime.h>
#include <cuda_fp16.h>
#include <math.h>
#include <stdint.h>

#define DIM 768
#define NHEAD 16
#define HD 48
#define SEQ 2048
#define ATTN_SCALE 0.14433756729740643f  // 1/sqrt(48)

#define BQ 128
#define BKV 64

// ---------------------------------------------------------------------------
// Scratch (device globals: allocation-guard-safe)
// ---------------------------------------------------------------------------
__device__ float g_q[8192 * DIM];
__device__ float g_k[8192 * DIM];
__device__ float g_v[8192 * DIM];
__device__ float g_ao[8192 * DIM];

// ---------------------------------------------------------------------------
// helpers
// ---------------------------------------------------------------------------
__device__ __forceinline__ uint32_t pk2(float lo, float hi) {
    __half2 h = __float22half2_rn(make_float2(lo, hi));
    return *(uint32_t*)&h;
}

__device__ __forceinline__ float fexp2(float x) {
    float y;
    asm("ex2.approx.f32 %0, %1;" : "=f"(y) : "f"(x));
    return y;
}

// D = A(16x16, row) * B(16x8, col) + D, fp16 in, fp32 accum
__device__ __forceinline__ void mma_f16(float* c, const uint32_t* a,
                                        uint32_t b0, uint32_t b1) {
    asm volatile(
        "mma.sync.aligned.m16n8k16.row.col.f32.f16.f16.f32 "
        "{%0,%1,%2,%3}, {%4,%5,%6,%7}, {%8,%9}, {%0,%1,%2,%3};\n"
        : "+f"(c[0]), "+f"(c[1]), "+f"(c[2]), "+f"(c[3])
        : "r"(a[0]), "r"(a[1]), "r"(a[2]), "r"(a[3]), "r"(b0), "r"(b1));
}

// ---------------------------------------------------------------------------
// GEMM (fp16 tensor core, fp32 accum): C[m][n] = sum_k A[m][k]*W[n][k] + b[n]
// Block tile 128x128, bk=32, 256 threads = 8 warps (2M x 4N),
// warp tile 64x32 = 4x4 m16n8 tiles, k16 mma. Register-prefetch.
// Shared: packed f16x2 words, [row][20] (16 data + 4 pad): fragment LDS
// pattern (20*g + tq) mod 32 = {0,20,8,28,16,4,24,12}+tq -> conflict-free.
// ---------------------------------------------------------------------------
__global__ __launch_bounds__(256) void gemm_nt_bias_f16(
    const float* __restrict__ A, const float* __restrict__ W,
    const float* __restrict__ bias, float* __restrict__ C,
    int M, int N, int K)
{
    __shared__ __align__(16) uint32_t As[128 * 20];
    __shared__ __align__(16) uint32_t Ws[128 * 20];

    const int tid  = threadIdx.x;
    const int lane = tid & 31;
    const int warp = tid >> 5;
    const int wm   = (warp >> 2) * 64;
    const int wn   = (warp & 3) * 32;
    const int g    = lane >> 2;
    const int tq   = lane & 3;

    const int bm = blockIdx.y * 128;
    const int bn = blockIdx.x * 128;

    float acc[4][4][4];
#pragma unroll
    for (int mi = 0; mi < 4; mi++)
#pragma unroll
        for (int ni = 0; ni < 4; ni++)
#pragma unroll
            for (int j = 0; j < 4; j++) acc[mi][ni][j] = 0.f;

    // staging slots: idx in [0,1024): row = idx>>3, c8 = idx&7 (float4 group)
    float4 pa[4], pw[4];
#pragma unroll
    for (int s = 0; s < 4; s++) {
        int idx = tid + s * 256;
        int row = idx >> 3, c8 = idx & 7;
        pa[s] = *(const float4*)(A + (size_t)(bm + row) * K + c8 * 4);
        pw[s] = *(const float4*)(W + (size_t)(bn + row) * K + c8 * 4);
    }

    for (int k0 = 0; k0 < K; k0 += 32) {
#pragma unroll
        for (int s = 0; s < 4; s++) {
            int idx = tid + s * 256;
            int row = idx >> 3, c8 = idx & 7;
            uint2 ua = make_uint2(pk2(pa[s].x, pa[s].y), pk2(pa[s].z, pa[s].w));
            uint2 uw = make_uint2(pk2(pw[s].x, pw[s].y), pk2(pw[s].z, pw[s].w));
            *(uint2*)&As[row * 20 + c8 * 2] = ua;
            *(uint2*)&Ws[row * 20 + c8 * 2] = uw;
        }
        __syncthreads();

        if (k0 + 32 < K) {
#pragma unroll
            for (int s = 0; s < 4; s++) {
                int idx = tid + s * 256;
                int row = idx >> 3, c8 = idx & 7;
                pa[s] = *(const float4*)(A + (size_t)(bm + row) * K + k0 + 32 + c8 * 4);
                pw[s] = *(const float4*)(W + (size_t)(bn + row) * K + k0 + 32 + c8 * 4);
            }
        }

#pragma unroll
        for (int kt = 0; kt < 2; kt++) {
            const int kwb = kt * 8;   // word offset of k16 chunk
            uint32_t af[4][4], bf[4][2];
#pragma unroll
            for (int mi = 0; mi < 4; mi++) {
                const int m = wm + mi * 16;
                af[mi][0] = As[(m + g) * 20 + kwb + tq];
                af[mi][1] = As[(m + 8 + g) * 20 + kwb + tq];
                af[mi][2] = As[(m + g) * 20 + kwb + 4 + tq];
                af[mi][3] = As[(m + 8 + g) * 20 + kwb + 4 + tq];
            }
#pragma unroll
            for (int ni = 0; ni < 4; ni++) {
                const int n = wn + ni * 8;
                bf[ni][0] = Ws[(n + g) * 20 + kwb + tq];
                bf[ni][1] = Ws[(n + g) * 20 + kwb + 4 + tq];
            }
#pragma unroll
            for (int mi = 0; mi < 4; mi++)
#pragma unroll
                for (int ni = 0; ni < 4; ni++)
                    mma_f16(acc[mi][ni], af[mi], bf[ni][0], bf[ni][1]);
        }
        __syncthreads();
    }

#pragma unroll
    for (int ni = 0; ni < 4; ni++) {
        const int col = bn + wn + ni * 8 + 2 * tq;
        const float2 bb = *(const float2*)(bias + col);
#pragma unroll
        for (int mi = 0; mi < 4; mi++) {
            const int row = bm + wm + mi * 16 + g;
            float2 v0, v1;
            v0.x = acc[mi][ni][0] + bb.x;
            v0.y = acc[mi][ni][1] + bb.y;
            v1.x = acc[mi][ni][2] + bb.x;
            v1.y = acc[mi][ni][3] + bb.y;
            *(float2*)(C + (size_t)row * N + col)       = v0;
            *(float2*)(C + (size_t)(row + 8) * N + col) = v1;
        }
    }
}

// ---------------------------------------------------------------------------
// Flash attention v6 (fp16 mma m16n8k16, fp32 softmax/accum).
// Block = 128 q rows of one (b,h), 128 threads = 4 warps; warp owns 32 rows
// (2 m16 subtiles). kv tiles of 64. One K/V fragment load feeds both subtiles.
//
// Shared (uint32 f16x2 words):
//   Ps[128][36]  [q][kv/2]   ofs 0     4608  (aliases Qs[128][28] staging)
//   Ks[64][28]   [kv][d/2]   ofs 4608  1792
//   Vt[48][36]   [d][kv/2]   ofs 6400  1728  (transposed pack: word=(kv2j,2j+1))
// total 8128 words = 32512 bytes. All fragment patterns conflict-free.
// ---------------------------------------------------------------------------
__global__ __launch_bounds__(128) void flash_attn_f16(
    const float* __restrict__ Q, const float* __restrict__ K,
    const float* __restrict__ V, float* __restrict__ O)
{
    extern __shared__ uint32_t usm[];
    uint32_t* Ps = usm;              // [128][36]
    uint32_t* Qs = usm;              // [128][28] staging alias
    uint32_t* Ks = usm + 4608;       // [64][28]
    uint32_t* Vt = usm + 6400;       // [48][36]

    const int tid  = threadIdx.x;
    const int lane = tid & 31;
    const int w    = tid >> 5;
    const int g    = lane >> 2;
    const int tq   = lane & 3;
    const int qw   = w * 32;

    const int h  = blockIdx.y;
    const int b  = blockIdx.z;
    const int q0 = blockIdx.x * BQ;

    const float* Qb = Q + ((size_t)(b * SEQ + q0)) * DIM + h * HD;
    const float* Kb = K + (size_t)b * SEQ * DIM + h * HD;
    const float* Vb = V + (size_t)b * SEQ * DIM + h * HD;

    // ---- stage Q packed fp16 (unscaled; scale folded into exp2 const) ----
#pragma unroll
    for (int i = 0; i < 12; i++) {
        int idx = tid + i * 128;
        int r   = idx / 12;
        int c4  = (idx % 12) << 2;
        float4 f = *(const float4*)(Qb + (size_t)r * DIM + c4);
        *(uint2*)&Qs[r * 28 + (c4 >> 1)] =
            make_uint2(pk2(f.x, f.y), pk2(f.z, f.w));
    }
    __syncthreads();

    // persistent Q fragments: 2 subtiles x 3 k16 chunks
    uint32_t qf[2][3][4];
#pragma unroll
    for (int sub = 0; sub < 2; sub++) {
        const int qb = qw + sub * 16;
#pragma unroll
        for (int kt = 0; kt < 3; kt++) {
            const int kwb = kt * 8;
            qf[sub][kt][0] = Qs[(qb + g) * 28 + kwb + tq];
            qf[sub][kt][1] = Qs[(qb + 8 + g) * 28 + kwb + tq];
            qf[sub][kt][2] = Qs[(qb + g) * 28 + kwb + 4 + tq];
            qf[sub][kt][3] = Qs[(qb + 8 + g) * 28 + kwb + 4 + tq];
        }
    }

    float oacc[2][6][4];
#pragma unroll
    for (int sub = 0; sub < 2; sub++)
#pragma unroll
        for (int ni = 0; ni < 6; ni++)
#pragma unroll
            for (int j = 0; j < 4; j++) oacc[sub][ni][j] = 0.f;
    float mrow[2][2] = {{-1e30f, -1e30f}, {-1e30f, -1e30f}};
    float lrow[2][2] = {{0.f, 0.f}, {0.f, 0.f}};

    const float CE = ATTN_SCALE * 1.4426950408889634f;  // scale * log2(e)

    for (int kv0 = 0; kv0 < SEQ; kv0 += BKV) {
        __syncthreads();  // all consumers of Ks/Vt (and Qs on iter 0) done

        // ---- stage K (row pack) ----
#pragma unroll
        for (int i = 0; i < 6; i++) {
            int idx = tid + i * 128;
            int r   = idx / 12;
            int c4  = (idx % 12) << 2;
            float4 kf = *(const float4*)(Kb + (size_t)(kv0 + r) * DIM + c4);
            *(uint2*)&Ks[r * 28 + (c4 >> 1)] =
                make_uint2(pk2(kf.x, kf.y), pk2(kf.z, kf.w));
        }
        // ---- stage V transposed pack: Vt[d][j] = {V[2j][d], V[2j+1][d]} ----
#pragma unroll
        for (int i = 0; i < 6; i++) {
            int idx = tid + i * 128;
            int j   = idx / 24;
            int c2  = (idx % 24) << 1;
            float2 v0 = *(const float2*)(Vb + (size_t)(kv0 + 2 * j) * DIM + c2);
            float2 v1 = *(const float2*)(Vb + (size_t)(kv0 + 2 * j + 1) * DIM + c2);
            Vt[c2 * 36 + j]       = pk2(v0.x, v1.x);
            Vt[(c2 + 1) * 36 + j] = pk2(v0.y, v1.y);
        }
        __syncthreads();

        // ---- S = Q K^T for BOTH subtiles, one K-fragment load each ----
        float sacc[2][8][4];
#pragma unroll
        for (int sub = 0; sub < 2; sub++)
#pragma unroll
            for (int ni = 0; ni < 8; ni++)
#pragma unroll
                for (int j = 0; j < 4; j++) sacc[sub][ni][j] = 0.f;

#pragma unroll
        for (int kt = 0; kt < 3; kt++) {
            const int kwb = kt * 8;
#pragma unroll
            for (int ni = 0; ni < 8; ni++) {
                const int n = ni * 8;
                uint32_t b0 = Ks[(n + g) * 28 + kwb + tq];
                uint32_t b1 = Ks[(n + g) * 28 + kwb + 4 + tq];
                mma_f16(sacc[0][ni], qf[0][kt], b0, b1);
                mma_f16(sacc[1][ni], qf[1][kt], b0, b1);
            }
        }

        // ---- online softmax + P write (packed fp16), per subtile ----
#pragma unroll
        for (int sub = 0; sub < 2; sub++) {
            const int qb = qw + sub * 16;

            float mx0 = -1e30f, mx1 = -1e30f;
#pragma unroll
            for (int ni = 0; ni < 8; ni++) {
                mx0 = fmaxf(mx0, fmaxf(sacc[sub][ni][0], sacc[sub][ni][1]));
                mx1 = fmaxf(mx1, fmaxf(sacc[sub][ni][2], sacc[sub][ni][3]));
            }
            mx0 = fmaxf(mx0, __shfl_xor_sync(0xffffffffu, mx0, 1));
            mx0 = fmaxf(mx0, __shfl_xor_sync(0xffffffffu, mx0, 2));
            mx1 = fmaxf(mx1, __shfl_xor_sync(0xffffffffu, mx1, 1));
            mx1 = fmaxf(mx1, __shfl_xor_sync(0xffffffffu, mx1, 2));

            const float mn0 = fmaxf(mrow[sub][0], mx0);
            const float mn1 = fmaxf(mrow[sub][1], mx1);
            const float cr0 = fexp2((mrow[sub][0] - mn0) * CE);
            const float cr1 = fexp2((mrow[sub][1] - mn1) * CE);
            mrow[sub][0] = mn0; mrow[sub][1] = mn1;

            float rs0 = 0.f, rs1 = 0.f;
#pragma unroll
            for (int ni = 0; ni < 8; ni++) {
                float p0 = fexp2((sacc[sub][ni][0] - mn0) * CE);
                float p1 = fexp2((sacc[sub][ni][1] - mn0) * CE);
                float p2 = fexp2((sacc[sub][ni][2] - mn1) * CE);
                float p3 = fexp2((sacc[sub][ni][3] - mn1) * CE);
                rs0 += p0 + p1;
                rs1 += p2 + p3;
                Ps[(qb + g) * 36 + 4 * ni + tq]     = pk2(p0, p1);
                Ps[(qb + 8 + g) * 36 + 4 * ni + tq] = pk2(p2, p3);
            }
            rs0 += __shfl_xor_sync(0xffffffffu, rs0, 1);
            rs0 += __shfl_xor_sync(0xffffffffu, rs0, 2);
            rs1 += __shfl_xor_sync(0xffffffffu, rs1, 1);
            rs1 += __shfl_xor_sync(0xffffffffu, rs1, 2);
            lrow[sub][0] = lrow[sub][0] * cr0 + rs0;
            lrow[sub][1] = lrow[sub][1] * cr1 + rs1;

#pragma unroll
            for (int ni = 0; ni < 6; ni++) {
                oacc[sub][ni][0] *= cr0; oacc[sub][ni][1] *= cr0;
                oacc[sub][ni][2] *= cr1; oacc[sub][ni][3] *= cr1;
            }
        }
        __syncwarp();  // P is warp-local

        // ---- O += P V : 4 k16 chunks, V frags loaded once for both subs ----
#pragma unroll
        for (int kt = 0; kt < 4; kt++) {
            const int kwb = kt * 8;
            uint32_t af0[4], af1[4];
            af0[0] = Ps[(qw + g) * 36 + kwb + tq];
            af0[1] = Ps[(qw + 8 + g) * 36 + kwb + tq];
            af0[2] = Ps[(qw + g) * 36 + kwb + 4 + tq];
            af0[3] = Ps[(qw + 8 + g) * 36 + kwb + 4 + tq];
            af1[0] = Ps[(qw + 16 + g) * 36 + kwb + tq];
            af1[1] = Ps[(qw + 24 + g) * 36 + kwb + tq];
            af1[2] = Ps[(qw + 16 + g) * 36 + kwb + 4 + tq];
            af1[3] = Ps[(qw + 24 + g) * 36 + kwb + 4 + tq];
#pragma unroll
            for (int ni = 0; ni < 6; ni++) {
                const int n = ni * 8;
                uint32_t b0 = Vt[(n + g) * 36 + kwb + tq];
                uint32_t b1 = Vt[(n + g) * 36 + kwb + 4 + tq];
                mma_f16(oacc[0][ni], af0, b0, b1);
                mma_f16(oacc[1][ni], af1, b0, b1);
            }
        }
    }

    // ---- epilogue ----
#pragma unroll
    for (int sub = 0; sub < 2; sub++) {
        const float inv0 = 1.f / lrow[sub][0];
        const float inv1 = 1.f / lrow[sub][1];
        float* Ob = O + ((size_t)(b * SEQ + q0 + qw + sub * 16)) * DIM + h * HD;
#pragma unroll
        for (int ni = 0; ni < 6; ni++) {
            const int col = ni * 8 + 2 * tq;
            float2 v0, v1;
            v0.x = oacc[sub][ni][0] * inv0; v0.y = oacc[sub][ni][1] * inv0;
            v1.x = oacc[sub][ni][2] * inv1; v1.y = oacc[sub][ni][3] * inv1;
            *(float2*)(Ob + (size_t)g * DIM + col)       = v0;
            *(float2*)(Ob + (size_t)(g + 8) * DIM + col) = v1;
        }
    }
}

// ---------------------------------------------------------------------------
// launch
// ---------------------------------------------------------------------------
extern "C" void kernel_launch(void* const* d_in, const int* in_sizes, int n_in,
                              void* d_out, int out_size)
{
    const float* x  = (const float*)d_in[0];
    const float* Wq = (const float*)d_in[1];
    const float* bq = (const float*)d_in[2];
    const float* Wk = (const float*)d_in[3];
    const float* bk = (const float*)d_in[4];
    const float* Wv = (const float*)d_in[5];
    const float* bv = (const float*)d_in[6];
    const float* Wo = (const float*)d_in[7];
    const float* bo = (const float*)d_in[8];
    float* out = (float*)d_out;

    const int M = in_sizes[0] / DIM;   // B*S = 8192
    const int B = M / SEQ;             // 4

    float *qp, *kp, *vp, *aop;
    cudaGetSymbolAddress((void**)&qp,  g_q);
    cudaGetSymbolAddress((void**)&kp,  g_k);
    cudaGetSymbolAddress((void**)&vp,  g_v);
    cudaGetSymbolAddress((void**)&aop, g_ao);

    const int attn_smem = 8128 * 4;    // 32512 bytes (< 48KB default)

    dim3 ggrid(DIM / 128, M / 128);    // (6, 64)
    gemm_nt_bias_f16<<<ggrid, 256>>>(x, Wq, bq, qp, M, DIM, DIM);
    gemm_nt_bias_f16<<<ggrid, 256>>>(x, Wk, bk, kp, M, DIM, DIM);
    gemm_nt_bias_f16<<<ggrid, 256>>>(x, Wv, bv, vp, M, DIM, DIM);

    dim3 agrid(SEQ / BQ, NHEAD, B);    // (16, 16, 4)
    flash_attn_f16<<<agrid, 128, attn_smem>>>(qp, kp, vp, aop);

    gemm_nt_bias_f16<<<ggrid, 256>>>(aop, Wo, bo, out, M, DIM, DIM);
}